// round 11
// baseline (speedup 1.0000x reference)
#include <cuda_runtime.h>
#include <cstdint>
#include <cstring>

// Problem dims
#define BDIM 64
#define TDIM 512
#define KDIM 1024   // IN_DIM
#define HDIM 1024   // HID
#define MTOT (BDIM * TDIM)   // 32768 rows of the GEMM

// exp(-1/20) rounded to nearest fp32
#define ALPHA 0.9512294245007140f

// Scratch for I = x @ W^T + b   (128 MB, static device allocation — guard-safe)
__device__ float g_I[(size_t)MTOT * HDIM];

typedef unsigned long long u64;

// packed fma: both lanes round exactly like scalar fma.rn.f32
__device__ __forceinline__ void fma2(u64& d, u64 a, u64 b) {
    asm("fma.rn.f32x2 %0, %1, %2, %0;" : "+l"(d) : "l"(a), "l"(b));
}
__device__ __forceinline__ u64 pack2(float lo, float hi) {
    u64 r;
    asm("mov.b64 %0, {%1, %2};" : "=l"(r) : "f"(lo), "f"(hi));
    return r;
}

// ---------------------------------------------------------------------------
// SGEMM (NT), Eigen-ordered accumulation (numerics VERIFIED R7/R9/R10):
//   per output: in-order FMA chain k ascending, fold (fadd) at k=1016,
//   fadd of 8-wide tail chain, fadd bias.
// FFMA2 v4: BM 128->64, 128 threads/CTA (per-thread work identical to R10)
// so 2-3 CTAs fit per SM — cross-CTA latency hiding kills the sync/LDS
// exposure seen at occ=1. Same FFMA2-issue and crossbar floors per SM.
// BM=64, BN=128, BK=8, TM=TN=8, 128 threads, 2-stage double buffer,
// peeled tail tile so only acc2 (64 regs) is loop-carried.
// ---------------------------------------------------------------------------
constexpr int BM = 64, BN = 128, BK = 8, TM = 8, TN = 8;
constexpr int NKB = KDIM / BK;       // 128 tiles; tiles 0..126 = k<1016

__global__ __launch_bounds__(128, 2) void sgemm_nt_bias_eigen_f32x2(
    const float* __restrict__ A,      // [MTOT, KDIM] row-major
    const float* __restrict__ W,      // [HDIM, KDIM] row-major
    const float* __restrict__ bias)   // [HDIM]
{
    __shared__ float As[2][BK][BM];   // As[buf][k][m]   (64 wide)
    __shared__ float Bs[2][BK][BN];   // Bs[buf][k][n]   (128 wide)

    const int cRow = blockIdx.y;      // 512 M tiles
    const int cCol = blockIdx.x;      // 8 N tiles
    const int tid  = threadIdx.x;     // 0..127

    const int threadCol = (tid % (BN / TN)) * TN;   // (tid%16)*8 : 0..120
    const int threadRow = (tid / (BN / TN)) * TM;   // (tid/16)*8 : 0..56

    // staging: A one float4/thread, B two float4/thread per k-tile
    const int innerRow = tid / 2;          // 0..63
    const int innerCol = (tid % 2) * 4;    // k offset 0 or 4

    const float* Aptr  = A + (size_t)cRow * BM * KDIM + (size_t)innerRow * KDIM + innerCol;
    const float* WptrL = W + (size_t)cCol * BN * KDIM + (size_t)innerRow * KDIM + innerCol;
    const float* WptrH = WptrL + (size_t)64 * KDIM;

    u64 acc2[TM * TN / 2];                 // pairs along N: 32 u64 = 64 regs
    #pragma unroll
    for (int i = 0; i < TM * TN / 2; i++) acc2[i] = 0ull;

    // ---- stage tile 0 ----
    float4 ra  = *reinterpret_cast<const float4*>(Aptr);
    float4 rbl = *reinterpret_cast<const float4*>(WptrL);
    float4 rbh = *reinterpret_cast<const float4*>(WptrH);
    {
        const float av[4] = {ra.x, ra.y, ra.z, ra.w};
        const float bl[4] = {rbl.x, rbl.y, rbl.z, rbl.w};
        const float bh[4] = {rbh.x, rbh.y, rbh.z, rbh.w};
        #pragma unroll
        for (int j = 0; j < 4; j++) {
            As[0][innerCol + j][innerRow]      = av[j];
            Bs[0][innerCol + j][innerRow]      = bl[j];
            Bs[0][innerCol + j][innerRow + 64] = bh[j];
        }
    }
    __syncthreads();

    // ---- compute one k-tile from buffer `buf` (k ascending, FFMA2 chains) ----
    auto compute_tile = [&](int buf) {
        #pragma unroll
        for (int k = 0; k < BK; k++) {
            float4 a0 = *reinterpret_cast<const float4*>(&As[buf][k][threadRow + 0]);
            float4 a1 = *reinterpret_cast<const float4*>(&As[buf][k][threadRow + 4]);
            float4 b0 = *reinterpret_cast<const float4*>(&Bs[buf][k][threadCol + 0]);
            float4 b1 = *reinterpret_cast<const float4*>(&Bs[buf][k][threadCol + 4]);

            u64 n[4];
            memcpy(&n[0], &b0.x, 8); memcpy(&n[1], &b0.z, 8);
            memcpy(&n[2], &b1.x, 8); memcpy(&n[3], &b1.z, 8);

            const float m[TM] = {a0.x, a0.y, a0.z, a0.w, a1.x, a1.y, a1.z, a1.w};
            #pragma unroll
            for (int i = 0; i < TM; i++) {
                const u64 mi = pack2(m[i], m[i]);   // ALU-pipe broadcast
                fma2(acc2[i * 4 + 0], mi, n[0]);
                fma2(acc2[i * 4 + 1], mi, n[1]);
                fma2(acc2[i * 4 + 2], mi, n[2]);
                fma2(acc2[i * 4 + 3], mi, n[3]);
            }
        }
    };

    // ---- main loop: tiles 0..126  (k = 0..1015, the Eigen kc=1016 panel) ----
    for (int kb = 0; kb < NKB - 1; kb++) {
        const int cur = kb & 1, nxt = cur ^ 1;

        // prefetch tile kb+1 (kb+1 <= 127, always valid)
        ra  = *reinterpret_cast<const float4*>(Aptr  + (size_t)(kb + 1) * BK);
        rbl = *reinterpret_cast<const float4*>(WptrL + (size_t)(kb + 1) * BK);
        rbh = *reinterpret_cast<const float4*>(WptrH + (size_t)(kb + 1) * BK);

        compute_tile(cur);

        const float av[4] = {ra.x, ra.y, ra.z, ra.w};
        const float bl[4] = {rbl.x, rbl.y, rbl.z, rbl.w};
        const float bh[4] = {rbh.x, rbh.y, rbh.z, rbh.w};
        #pragma unroll
        for (int j = 0; j < 4; j++) {
            As[nxt][innerCol + j][innerRow]      = av[j];
            Bs[nxt][innerCol + j][innerRow]      = bl[j];
            Bs[nxt][innerCol + j][innerRow + 64] = bh[j];
        }
        __syncthreads();
    }

    // ---- Eigen fold at k=1016: sum <- chain  (bitwise == fadd(0, chain)) ----
    u64 sum2[TM * TN / 2];
    #pragma unroll
    for (int i = 0; i < TM * TN / 2; i++) { sum2[i] = acc2[i]; acc2[i] = 0ull; }

    // ---- tail tile 127 (k = 1016..1023) ----
    compute_tile((NKB - 1) & 1);

    // ---- epilogue: o = fadd(fadd(sum, tail), bias)  (scalar, exactly R7) ----
    #pragma unroll
    for (int i = 0; i < TM; i++) {
        const size_t row = (size_t)cRow * BM + threadRow + i;
        #pragma unroll
        for (int half = 0; half < 2; half++) {
            const int col = cCol * BN + threadCol + half * 4;
            float4 bv = *reinterpret_cast<const float4*>(&bias[col]);
            float s[4], t[4];
            memcpy(&s[0], &sum2[i * 4 + half * 2 + 0], 8);
            memcpy(&s[2], &sum2[i * 4 + half * 2 + 1], 8);
            memcpy(&t[0], &acc2[i * 4 + half * 2 + 0], 8);
            memcpy(&t[2], &acc2[i * 4 + half * 2 + 1], 8);
            float4 o;
            o.x = __fadd_rn(__fadd_rn(s[0], t[0]), bv.x);
            o.y = __fadd_rn(__fadd_rn(s[1], t[1]), bv.y);
            o.z = __fadd_rn(__fadd_rn(s[2], t[2]), bv.z);
            o.w = __fadd_rn(__fadd_rn(s[3], t[3]), bv.w);
            *reinterpret_cast<float4*>(&g_I[row * HDIM + col]) = o;
        }
    }
}

// ---------------------------------------------------------------------------
// LIF scan — EXACT R7 version (62.6 us measured). Do not touch.
// ---------------------------------------------------------------------------
__global__ __launch_bounds__(256) void lif_scan(
    float* __restrict__ spikes,      // [B,T,H]
    float* __restrict__ mem_final)   // [B,H]
{
    const int idx = blockIdx.x * blockDim.x + threadIdx.x;  // over B*H
    const int b = idx / HDIM;
    const int h = idx % HDIM;

    const float* Ip = g_I + (size_t)b * TDIM * HDIM + h;
    float* Sp = spikes + (size_t)b * TDIM * HDIM + h;

    float mem = 0.0f;
    #pragma unroll 8
    for (int t = 0; t < TDIM; t++) {
        mem = __fadd_rn(__fmul_rn(ALPHA, mem), Ip[(size_t)t * HDIM]);
        const bool fire = (mem >= 1.0f);
        Sp[(size_t)t * HDIM] = fire ? 1.0f : 0.0f;
        mem = fire ? 0.0f : mem;
    }
    mem_final[idx] = mem;
}

// ---------------------------------------------------------------------------
extern "C" void kernel_launch(void* const* d_in, const int* in_sizes, int n_in,
                              void* d_out, int out_size)
{
    const float* x  = (const float*)d_in[0];   // [B,T,IN]
    const float* W  = (const float*)d_in[1];   // [HID,IN]
    const float* b  = (const float*)d_in[2];   // [HID]

    float* out      = (float*)d_out;
    float* spikes   = out;                                   // B*T*H floats
    float* mem_fin  = out + (size_t)MTOT * HDIM;             // B*H floats

    // GEMM: I = x @ W^T + b   (Eigen kc=1016 ordering, FFMA2 v4, occ>=2)
    dim3 gemmGrid(HDIM / BN, MTOT / BM);   // (8, 512)
    sgemm_nt_bias_eigen_f32x2<<<gemmGrid, 128>>>(x, W, b);

    // LIF scan over T
    lif_scan<<<(BDIM * HDIM) / 256, 256>>>(spikes, mem_fin);
}

// round 12
// speedup vs baseline: 1.1996x; 1.1996x over previous
#include <cuda_runtime.h>
#include <cstdint>
#include <cstring>

// Problem dims
#define BDIM 64
#define TDIM 512
#define KDIM 1024   // IN_DIM
#define HDIM 1024   // HID
#define MTOT (BDIM * TDIM)   // 32768 rows of the GEMM

// exp(-1/20) rounded to nearest fp32
#define ALPHA 0.9512294245007140f

// Scratch for I = x @ W^T + b   (128 MB, static device allocation — guard-safe)
__device__ float g_I[(size_t)MTOT * HDIM];

typedef unsigned long long u64;

// packed fma: both lanes round exactly like scalar fma.rn.f32
__device__ __forceinline__ void fma2(u64& d, u64 a, u64 b) {
    asm("fma.rn.f32x2 %0, %1, %2, %0;" : "+l"(d) : "l"(a), "l"(b));
}
__device__ __forceinline__ u64 pack2(float lo, float hi) {
    u64 r;
    asm("mov.b64 %0, {%1, %2};" : "=l"(r) : "f"(lo), "f"(hi));
    return r;
}

// ---------------------------------------------------------------------------
// SGEMM (NT), Eigen-ordered accumulation (numerics VERIFIED R7/R9/R10/R11):
//   per output: in-order FMA chain k ascending, fold (fadd) at k=1016,
//   fadd of 8-wide tail chain, fadd bias.
// FFMA2 v5 (= R10 shape + conflict-free B mapping):
//   Thread c = tid%16 owns N-cols {4c..4c+3} and {64+4c..64+4c+3}.
//   B loads across a warp's 16 unique lanes are byte-contiguous (stride 16B)
//   -> zero smem bank conflicts (was 4-way at stride 32B with the 8c mapping).
// BM=128, BN=128, BK=8, TM=TN=8, 256 threads, 2-stage double buffer,
// peeled tail tile so only acc2 (64 regs) is loop-carried.
// ---------------------------------------------------------------------------
constexpr int BM = 128, BN = 128, BK = 8, TM = 8, TN = 8;
constexpr int NKB = KDIM / BK;       // 128 tiles; tiles 0..126 = k<1016

__global__ __launch_bounds__(256, 1) void sgemm_nt_bias_eigen_f32x2(
    const float* __restrict__ A,      // [MTOT, KDIM] row-major
    const float* __restrict__ W,      // [HDIM, KDIM] row-major
    const float* __restrict__ bias)   // [HDIM]
{
    __shared__ float As[2][BK][BM];   // As[buf][k][m]
    __shared__ float Bs[2][BK][BN];   // Bs[buf][k][n]

    const int cRow = blockIdx.y;
    const int cCol = blockIdx.x;
    const int tid  = threadIdx.x;

    const int threadRow = (tid / 16) * TM;   // 0..120 (warp-broadcast A)
    const int colLo     = (tid % 16) * 4;    // cols colLo..colLo+3
    const int colHi     = colLo + 64;        // cols colHi..colHi+3

    // staging: one float4 per matrix per thread per k-tile
    const int innerRow = tid / 2;          // 0..127 (m or n index)
    const int innerCol = (tid % 2) * 4;    // k offset 0 or 4

    const float* Aptr = A + (size_t)cRow * BM * KDIM + (size_t)innerRow * KDIM + innerCol;
    const float* Wptr = W + (size_t)cCol * BN * KDIM + (size_t)innerRow * KDIM + innerCol;

    u64 acc2[TM * TN / 2];                 // pairs along N: 32 u64 = 64 regs
    #pragma unroll
    for (int i = 0; i < TM * TN / 2; i++) acc2[i] = 0ull;

    // ---- stage tile 0 ----
    float4 ra = *reinterpret_cast<const float4*>(Aptr);
    float4 rb = *reinterpret_cast<const float4*>(Wptr);
    {
        const float av[4] = {ra.x, ra.y, ra.z, ra.w};
        const float bv[4] = {rb.x, rb.y, rb.z, rb.w};
        #pragma unroll
        for (int j = 0; j < 4; j++) {
            As[0][innerCol + j][innerRow] = av[j];
            Bs[0][innerCol + j][innerRow] = bv[j];
        }
    }
    __syncthreads();

    // ---- compute one k-tile from buffer `buf` (k ascending, FFMA2 chains) ----
    auto compute_tile = [&](int buf) {
        #pragma unroll
        for (int k = 0; k < BK; k++) {
            float4 a0 = *reinterpret_cast<const float4*>(&As[buf][k][threadRow + 0]);
            float4 a1 = *reinterpret_cast<const float4*>(&As[buf][k][threadRow + 4]);
            float4 b0 = *reinterpret_cast<const float4*>(&Bs[buf][k][colLo]);  // contiguous across lanes
            float4 b1 = *reinterpret_cast<const float4*>(&Bs[buf][k][colHi]);

            u64 n[4];
            memcpy(&n[0], &b0.x, 8); memcpy(&n[1], &b0.z, 8);
            memcpy(&n[2], &b1.x, 8); memcpy(&n[3], &b1.z, 8);

            const float m[TM] = {a0.x, a0.y, a0.z, a0.w, a1.x, a1.y, a1.z, a1.w};
            #pragma unroll
            for (int i = 0; i < TM; i++) {
                const u64 mi = pack2(m[i], m[i]);   // ALU-pipe broadcast
                fma2(acc2[i * 4 + 0], mi, n[0]);    // cols (colLo,   colLo+1)
                fma2(acc2[i * 4 + 1], mi, n[1]);    // cols (colLo+2, colLo+3)
                fma2(acc2[i * 4 + 2], mi, n[2]);    // cols (colHi,   colHi+1)
                fma2(acc2[i * 4 + 3], mi, n[3]);    // cols (colHi+2, colHi+3)
            }
        }
    };

    // ---- main loop: tiles 0..126  (k = 0..1015, the Eigen kc=1016 panel) ----
    for (int kb = 0; kb < NKB - 1; kb++) {
        const int cur = kb & 1, nxt = cur ^ 1;

        // prefetch tile kb+1 (kb+1 <= 127, always valid)
        ra = *reinterpret_cast<const float4*>(Aptr + (size_t)(kb + 1) * BK);
        rb = *reinterpret_cast<const float4*>(Wptr + (size_t)(kb + 1) * BK);

        compute_tile(cur);

        const float av[4] = {ra.x, ra.y, ra.z, ra.w};
        const float bv[4] = {rb.x, rb.y, rb.z, rb.w};
        #pragma unroll
        for (int j = 0; j < 4; j++) {
            As[nxt][innerCol + j][innerRow] = av[j];
            Bs[nxt][innerCol + j][innerRow] = bv[j];
        }
        __syncthreads();
    }

    // ---- Eigen fold at k=1016: sum <- chain  (bitwise == fadd(0, chain)) ----
    u64 sum2[TM * TN / 2];
    #pragma unroll
    for (int i = 0; i < TM * TN / 2; i++) { sum2[i] = acc2[i]; acc2[i] = 0ull; }

    // ---- tail tile 127 (k = 1016..1023) ----
    compute_tile((NKB - 1) & 1);

    // ---- epilogue: o = fadd(fadd(sum, tail), bias)  (scalar, exactly R7) ----
    #pragma unroll
    for (int i = 0; i < TM; i++) {
        const size_t row = (size_t)cRow * BM + threadRow + i;
        #pragma unroll
        for (int half = 0; half < 2; half++) {
            const int col = cCol * BN + (half == 0 ? colLo : colHi);
            float4 bv = *reinterpret_cast<const float4*>(&bias[col]);
            float s[4], t[4];
            memcpy(&s[0], &sum2[i * 4 + half * 2 + 0], 8);
            memcpy(&s[2], &sum2[i * 4 + half * 2 + 1], 8);
            memcpy(&t[0], &acc2[i * 4 + half * 2 + 0], 8);
            memcpy(&t[2], &acc2[i * 4 + half * 2 + 1], 8);
            float4 o;
            o.x = __fadd_rn(__fadd_rn(s[0], t[0]), bv.x);
            o.y = __fadd_rn(__fadd_rn(s[1], t[1]), bv.y);
            o.z = __fadd_rn(__fadd_rn(s[2], t[2]), bv.z);
            o.w = __fadd_rn(__fadd_rn(s[3], t[3]), bv.w);
            *reinterpret_cast<float4*>(&g_I[row * HDIM + col]) = o;
        }
    }
}

// ---------------------------------------------------------------------------
// LIF scan — EXACT R7 version (62.6 us measured). Do not touch.
// ---------------------------------------------------------------------------
__global__ __launch_bounds__(256) void lif_scan(
    float* __restrict__ spikes,      // [B,T,H]
    float* __restrict__ mem_final)   // [B,H]
{
    const int idx = blockIdx.x * blockDim.x + threadIdx.x;  // over B*H
    const int b = idx / HDIM;
    const int h = idx % HDIM;

    const float* Ip = g_I + (size_t)b * TDIM * HDIM + h;
    float* Sp = spikes + (size_t)b * TDIM * HDIM + h;

    float mem = 0.0f;
    #pragma unroll 8
    for (int t = 0; t < TDIM; t++) {
        mem = __fadd_rn(__fmul_rn(ALPHA, mem), Ip[(size_t)t * HDIM]);
        const bool fire = (mem >= 1.0f);
        Sp[(size_t)t * HDIM] = fire ? 1.0f : 0.0f;
        mem = fire ? 0.0f : mem;
    }
    mem_final[idx] = mem;
}

// ---------------------------------------------------------------------------
extern "C" void kernel_launch(void* const* d_in, const int* in_sizes, int n_in,
                              void* d_out, int out_size)
{
    const float* x  = (const float*)d_in[0];   // [B,T,IN]
    const float* W  = (const float*)d_in[1];   // [HID,IN]
    const float* b  = (const float*)d_in[2];   // [HID]

    float* out      = (float*)d_out;
    float* spikes   = out;                                   // B*T*H floats
    float* mem_fin  = out + (size_t)MTOT * HDIM;             // B*H floats

    // GEMM: I = x @ W^T + b   (Eigen kc=1016 ordering, FFMA2 v5)
    dim3 gemmGrid(HDIM / BN, MTOT / BM);   // (8, 256)
    sgemm_nt_bias_eigen_f32x2<<<gemmGrid, 256>>>(x, W, b);

    // LIF scan over T
    lif_scan<<<(BDIM * HDIM) / 256, 256>>>(spikes, mem_fin);
}

// round 13
// speedup vs baseline: 1.2017x; 1.0017x over previous
#include <cuda_runtime.h>
#include <cstdint>
#include <cstring>

// Problem dims
#define BDIM 64
#define TDIM 512
#define KDIM 1024   // IN_DIM
#define HDIM 1024   // HID
#define MTOT (BDIM * TDIM)   // 32768 rows of the GEMM

// exp(-1/20) rounded to nearest fp32
#define ALPHA 0.9512294245007140f

// Scratch for I = x @ W^T + b   (128 MB, static device allocation — guard-safe)
__device__ float g_I[(size_t)MTOT * HDIM];

typedef unsigned long long u64;

// packed fma: both lanes round exactly like scalar fma.rn.f32
__device__ __forceinline__ void fma2(u64& d, u64 a, u64 b) {
    asm("fma.rn.f32x2 %0, %1, %2, %0;" : "+l"(d) : "l"(a), "l"(b));
}
__device__ __forceinline__ u64 pack2(float lo, float hi) {
    u64 r;
    asm("mov.b64 %0, {%1, %2};" : "=l"(r) : "f"(lo), "f"(hi));
    return r;
}

// ---------------------------------------------------------------------------
// SGEMM (NT), Eigen-ordered accumulation (numerics VERIFIED R7/R9-R12):
//   per output: in-order FMA chain k ascending, fold (fadd) at k=1016,
//   fadd of 8-wide tail chain, fadd bias.
// FFMA2 v6 (= R12 + reuse-cache-friendly inner nest):
//   FFMA2 reads 3 register pairs -> 3 even + 3 odd distinct banks -> rt 3
//   (RF-banking rule). Keeping one operand in the SAME source slot across
//   consecutive FFMA2 lets the operand-reuse latch drop it to rt 2.
//   Nest swapped to p-outer / i-inner: n[p] lives in slot-b for 8 straight
//   FFMA2 (longest possible reuse run). Chain order per output unchanged.
// BM=128, BN=128, BK=8, TM=TN=8, 256 threads, conflict-free B mapping,
// 2-stage double buffer, peeled tail tile (only acc2 loop-carried).
// ---------------------------------------------------------------------------
constexpr int BM = 128, BN = 128, BK = 8, TM = 8, TN = 8;
constexpr int NKB = KDIM / BK;       // 128 tiles; tiles 0..126 = k<1016

__global__ __launch_bounds__(256, 1) void sgemm_nt_bias_eigen_f32x2(
    const float* __restrict__ A,      // [MTOT, KDIM] row-major
    const float* __restrict__ W,      // [HDIM, KDIM] row-major
    const float* __restrict__ bias)   // [HDIM]
{
    __shared__ float As[2][BK][BM];   // As[buf][k][m]
    __shared__ float Bs[2][BK][BN];   // Bs[buf][k][n]

    const int cRow = blockIdx.y;
    const int cCol = blockIdx.x;
    const int tid  = threadIdx.x;

    const int threadRow = (tid / 16) * TM;   // 0..120 (warp-broadcast A)
    const int colLo     = (tid % 16) * 4;    // cols colLo..colLo+3
    const int colHi     = colLo + 64;        // cols colHi..colHi+3

    // staging: one float4 per matrix per thread per k-tile
    const int innerRow = tid / 2;          // 0..127 (m or n index)
    const int innerCol = (tid % 2) * 4;    // k offset 0 or 4

    const float* Aptr = A + (size_t)cRow * BM * KDIM + (size_t)innerRow * KDIM + innerCol;
    const float* Wptr = W + (size_t)cCol * BN * KDIM + (size_t)innerRow * KDIM + innerCol;

    u64 acc2[TM * TN / 2];                 // pairs along N: 32 u64 = 64 regs
    #pragma unroll
    for (int i = 0; i < TM * TN / 2; i++) acc2[i] = 0ull;

    // ---- stage tile 0 ----
    float4 ra = *reinterpret_cast<const float4*>(Aptr);
    float4 rb = *reinterpret_cast<const float4*>(Wptr);
    {
        const float av[4] = {ra.x, ra.y, ra.z, ra.w};
        const float bv[4] = {rb.x, rb.y, rb.z, rb.w};
        #pragma unroll
        for (int j = 0; j < 4; j++) {
            As[0][innerCol + j][innerRow] = av[j];
            Bs[0][innerCol + j][innerRow] = bv[j];
        }
    }
    __syncthreads();

    // ---- compute one k-tile from buffer `buf` (k ascending, FFMA2 chains) ----
    auto compute_tile = [&](int buf) {
        #pragma unroll
        for (int k = 0; k < BK; k++) {
            float4 a0 = *reinterpret_cast<const float4*>(&As[buf][k][threadRow + 0]);
            float4 a1 = *reinterpret_cast<const float4*>(&As[buf][k][threadRow + 4]);
            float4 b0 = *reinterpret_cast<const float4*>(&Bs[buf][k][colLo]);  // contiguous across lanes
            float4 b1 = *reinterpret_cast<const float4*>(&Bs[buf][k][colHi]);

            u64 n[4];
            memcpy(&n[0], &b0.x, 8); memcpy(&n[1], &b0.z, 8);
            memcpy(&n[2], &b1.x, 8); memcpy(&n[3], &b1.z, 8);

            const float mv[TM] = {a0.x, a0.y, a0.z, a0.w, a1.x, a1.y, a1.z, a1.w};
            u64 m2[TM];
            #pragma unroll
            for (int i = 0; i < TM; i++) m2[i] = pack2(mv[i], mv[i]);  // ALU pipe

            // p-outer / i-inner: n[p] stays in slot-b for 8 consecutive FFMA2
            // -> operand-reuse latch; per-output k-chain order unchanged.
            #pragma unroll
            for (int p = 0; p < 4; p++) {
                #pragma unroll
                for (int i = 0; i < TM; i++) {
                    fma2(acc2[i * 4 + p], m2[i], n[p]);
                }
            }
        }
    };

    // ---- main loop: tiles 0..126  (k = 0..1015, the Eigen kc=1016 panel) ----
    for (int kb = 0; kb < NKB - 1; kb++) {
        const int cur = kb & 1, nxt = cur ^ 1;

        // prefetch tile kb+1 (kb+1 <= 127, always valid)
        ra = *reinterpret_cast<const float4*>(Aptr + (size_t)(kb + 1) * BK);
        rb = *reinterpret_cast<const float4*>(Wptr + (size_t)(kb + 1) * BK);

        compute_tile(cur);

        const float av[4] = {ra.x, ra.y, ra.z, ra.w};
        const float bv[4] = {rb.x, rb.y, rb.z, rb.w};
        #pragma unroll
        for (int j = 0; j < 4; j++) {
            As[nxt][innerCol + j][innerRow] = av[j];
            Bs[nxt][innerCol + j][innerRow] = bv[j];
        }
        __syncthreads();
    }

    // ---- Eigen fold at k=1016: sum <- chain  (bitwise == fadd(0, chain)) ----
    u64 sum2[TM * TN / 2];
    #pragma unroll
    for (int i = 0; i < TM * TN / 2; i++) { sum2[i] = acc2[i]; acc2[i] = 0ull; }

    // ---- tail tile 127 (k = 1016..1023) ----
    compute_tile((NKB - 1) & 1);

    // ---- epilogue: o = fadd(fadd(sum, tail), bias)  (scalar, exactly R7) ----
    #pragma unroll
    for (int i = 0; i < TM; i++) {
        const size_t row = (size_t)cRow * BM + threadRow + i;
        #pragma unroll
        for (int half = 0; half < 2; half++) {
            const int col = cCol * BN + (half == 0 ? colLo : colHi);
            float4 bv = *reinterpret_cast<const float4*>(&bias[col]);
            float s[4], t[4];
            memcpy(&s[0], &sum2[i * 4 + half * 2 + 0], 8);
            memcpy(&s[2], &sum2[i * 4 + half * 2 + 1], 8);
            memcpy(&t[0], &acc2[i * 4 + half * 2 + 0], 8);
            memcpy(&t[2], &acc2[i * 4 + half * 2 + 1], 8);
            float4 o;
            o.x = __fadd_rn(__fadd_rn(s[0], t[0]), bv.x);
            o.y = __fadd_rn(__fadd_rn(s[1], t[1]), bv.y);
            o.z = __fadd_rn(__fadd_rn(s[2], t[2]), bv.z);
            o.w = __fadd_rn(__fadd_rn(s[3], t[3]), bv.w);
            *reinterpret_cast<float4*>(&g_I[row * HDIM + col]) = o;
        }
    }
}

// ---------------------------------------------------------------------------
// LIF scan — EXACT R7 version (62.6 us measured). Do not touch.
// ---------------------------------------------------------------------------
__global__ __launch_bounds__(256) void lif_scan(
    float* __restrict__ spikes,      // [B,T,H]
    float* __restrict__ mem_final)   // [B,H]
{
    const int idx = blockIdx.x * blockDim.x + threadIdx.x;  // over B*H
    const int b = idx / HDIM;
    const int h = idx % HDIM;

    const float* Ip = g_I + (size_t)b * TDIM * HDIM + h;
    float* Sp = spikes + (size_t)b * TDIM * HDIM + h;

    float mem = 0.0f;
    #pragma unroll 8
    for (int t = 0; t < TDIM; t++) {
        mem = __fadd_rn(__fmul_rn(ALPHA, mem), Ip[(size_t)t * HDIM]);
        const bool fire = (mem >= 1.0f);
        Sp[(size_t)t * HDIM] = fire ? 1.0f : 0.0f;
        mem = fire ? 0.0f : mem;
    }
    mem_final[idx] = mem;
}

// ---------------------------------------------------------------------------
extern "C" void kernel_launch(void* const* d_in, const int* in_sizes, int n_in,
                              void* d_out, int out_size)
{
    const float* x  = (const float*)d_in[0];   // [B,T,IN]
    const float* W  = (const float*)d_in[1];   // [HID,IN]
    const float* b  = (const float*)d_in[2];   // [HID]

    float* out      = (float*)d_out;
    float* spikes   = out;                                   // B*T*H floats
    float* mem_fin  = out + (size_t)MTOT * HDIM;             // B*H floats

    // GEMM: I = x @ W^T + b   (Eigen kc=1016 ordering, FFMA2 v6)
    dim3 gemmGrid(HDIM / BN, MTOT / BM);   // (8, 256)
    sgemm_nt_bias_eigen_f32x2<<<gemmGrid, 256>>>(x, W, b);

    // LIF scan over T
    lif_scan<<<(BDIM * HDIM) / 256, 256>>>(spikes, mem_fin);
}

// round 14
// speedup vs baseline: 1.2177x; 1.0133x over previous
#include <cuda_runtime.h>
#include <cstdint>
#include <cstring>

// Problem dims
#define BDIM 64
#define TDIM 512
#define KDIM 1024   // IN_DIM
#define HDIM 1024   // HID
#define MTOT (BDIM * TDIM)   // 32768 rows of the GEMM

// exp(-1/20) rounded to nearest fp32
#define ALPHA 0.9512294245007140f

// Scratch for I = x @ W^T + b   (128 MB, static device allocation — guard-safe)
__device__ float g_I[(size_t)MTOT * HDIM];

typedef unsigned long long u64;

// packed fma: both lanes round exactly like scalar fma.rn.f32
__device__ __forceinline__ void fma2(u64& d, u64 a, u64 b) {
    asm("fma.rn.f32x2 %0, %1, %2, %0;" : "+l"(d) : "l"(a), "l"(b));
}
__device__ __forceinline__ u64 pack2(float lo, float hi) {
    u64 r;
    asm("mov.b64 %0, {%1, %2};" : "=l"(r) : "f"(lo), "f"(hi));
    return r;
}

// ---------------------------------------------------------------------------
// SGEMM (NT), Eigen-ordered accumulation (numerics VERIFIED R7/R9-R13):
//   per output: in-order FMA chain k ascending, fold (fadd) at k=1016,
//   fadd of 8-wide tail chain, fadd bias.
// FFMA2 v6 — measured AT the structural floor (64 FFMA2 x rt3 = 192
// cyc/k-step/SMSP at NAT-max clock). FROZEN: R11 (occ), R13 (reuse order)
// both proved neutral; R12's conflict-free B mapping is load-bearing.
// BM=128, BN=128, BK=8, TM=TN=8, 256 threads, 2-stage double buffer,
// peeled tail tile (only acc2 loop-carried).
// ---------------------------------------------------------------------------
constexpr int BM = 128, BN = 128, BK = 8, TM = 8, TN = 8;
constexpr int NKB = KDIM / BK;       // 128 tiles; tiles 0..126 = k<1016

__global__ __launch_bounds__(256, 1) void sgemm_nt_bias_eigen_f32x2(
    const float* __restrict__ A,      // [MTOT, KDIM] row-major
    const float* __restrict__ W,      // [HDIM, KDIM] row-major
    const float* __restrict__ bias)   // [HDIM]
{
    __shared__ float As[2][BK][BM];   // As[buf][k][m]
    __shared__ float Bs[2][BK][BN];   // Bs[buf][k][n]

    const int cRow = blockIdx.y;
    const int cCol = blockIdx.x;
    const int tid  = threadIdx.x;

    const int threadRow = (tid / 16) * TM;   // 0..120 (warp-broadcast A)
    const int colLo     = (tid % 16) * 4;    // cols colLo..colLo+3
    const int colHi     = colLo + 64;        // cols colHi..colHi+3

    // staging: one float4 per matrix per thread per k-tile
    const int innerRow = tid / 2;          // 0..127 (m or n index)
    const int innerCol = (tid % 2) * 4;    // k offset 0 or 4

    const float* Aptr = A + (size_t)cRow * BM * KDIM + (size_t)innerRow * KDIM + innerCol;
    const float* Wptr = W + (size_t)cCol * BN * KDIM + (size_t)innerRow * KDIM + innerCol;

    u64 acc2[TM * TN / 2];                 // pairs along N: 32 u64 = 64 regs
    #pragma unroll
    for (int i = 0; i < TM * TN / 2; i++) acc2[i] = 0ull;

    // ---- stage tile 0 ----
    float4 ra = *reinterpret_cast<const float4*>(Aptr);
    float4 rb = *reinterpret_cast<const float4*>(Wptr);
    {
        const float av[4] = {ra.x, ra.y, ra.z, ra.w};
        const float bv[4] = {rb.x, rb.y, rb.z, rb.w};
        #pragma unroll
        for (int j = 0; j < 4; j++) {
            As[0][innerCol + j][innerRow] = av[j];
            Bs[0][innerCol + j][innerRow] = bv[j];
        }
    }
    __syncthreads();

    // ---- compute one k-tile from buffer `buf` (k ascending, FFMA2 chains) ----
    auto compute_tile = [&](int buf) {
        #pragma unroll
        for (int k = 0; k < BK; k++) {
            float4 a0 = *reinterpret_cast<const float4*>(&As[buf][k][threadRow + 0]);
            float4 a1 = *reinterpret_cast<const float4*>(&As[buf][k][threadRow + 4]);
            float4 b0 = *reinterpret_cast<const float4*>(&Bs[buf][k][colLo]);  // contiguous across lanes
            float4 b1 = *reinterpret_cast<const float4*>(&Bs[buf][k][colHi]);

            u64 n[4];
            memcpy(&n[0], &b0.x, 8); memcpy(&n[1], &b0.z, 8);
            memcpy(&n[2], &b1.x, 8); memcpy(&n[3], &b1.z, 8);

            const float mv[TM] = {a0.x, a0.y, a0.z, a0.w, a1.x, a1.y, a1.z, a1.w};
            u64 m2[TM];
            #pragma unroll
            for (int i = 0; i < TM; i++) m2[i] = pack2(mv[i], mv[i]);  // ALU pipe

            #pragma unroll
            for (int p = 0; p < 4; p++) {
                #pragma unroll
                for (int i = 0; i < TM; i++) {
                    fma2(acc2[i * 4 + p], m2[i], n[p]);
                }
            }
        }
    };

    // ---- main loop: tiles 0..126  (k = 0..1015, the Eigen kc=1016 panel) ----
    for (int kb = 0; kb < NKB - 1; kb++) {
        const int cur = kb & 1, nxt = cur ^ 1;

        // prefetch tile kb+1 (kb+1 <= 127, always valid)
        ra = *reinterpret_cast<const float4*>(Aptr + (size_t)(kb + 1) * BK);
        rb = *reinterpret_cast<const float4*>(Wptr + (size_t)(kb + 1) * BK);

        compute_tile(cur);

        const float av[4] = {ra.x, ra.y, ra.z, ra.w};
        const float bv[4] = {rb.x, rb.y, rb.z, rb.w};
        #pragma unroll
        for (int j = 0; j < 4; j++) {
            As[nxt][innerCol + j][innerRow] = av[j];
            Bs[nxt][innerCol + j][innerRow] = bv[j];
        }
        __syncthreads();
    }

    // ---- Eigen fold at k=1016: sum <- chain  (bitwise == fadd(0, chain)) ----
    u64 sum2[TM * TN / 2];
    #pragma unroll
    for (int i = 0; i < TM * TN / 2; i++) { sum2[i] = acc2[i]; acc2[i] = 0ull; }

    // ---- tail tile 127 (k = 1016..1023) ----
    compute_tile((NKB - 1) & 1);

    // ---- epilogue: o = fadd(fadd(sum, tail), bias)  (scalar, exactly R7) ----
    #pragma unroll
    for (int i = 0; i < TM; i++) {
        const size_t row = (size_t)cRow * BM + threadRow + i;
        #pragma unroll
        for (int half = 0; half < 2; half++) {
            const int col = cCol * BN + (half == 0 ? colLo : colHi);
            float4 bv = *reinterpret_cast<const float4*>(&bias[col]);
            float s[4], t[4];
            memcpy(&s[0], &sum2[i * 4 + half * 2 + 0], 8);
            memcpy(&s[2], &sum2[i * 4 + half * 2 + 1], 8);
            memcpy(&t[0], &acc2[i * 4 + half * 2 + 0], 8);
            memcpy(&t[2], &acc2[i * 4 + half * 2 + 1], 8);
            float4 o;
            o.x = __fadd_rn(__fadd_rn(s[0], t[0]), bv.x);
            o.y = __fadd_rn(__fadd_rn(s[1], t[1]), bv.y);
            o.z = __fadd_rn(__fadd_rn(s[2], t[2]), bv.z);
            o.w = __fadd_rn(__fadd_rn(s[3], t[3]), bv.w);
            *reinterpret_cast<float4*>(&g_I[row * HDIM + col]) = o;
        }
    }
}

// ---------------------------------------------------------------------------
// LIF scan v2: chunked prefetch — 16 independent LDGs batched into registers
// (MLP=16), then 16 sequential compute+store steps. Arithmetic sequence per
// (b,h) is IDENTICAL to R7's loop (same fmul/fadd order on same values)
// -> bitwise-identical output. Plain loads/stores (R8 proved the ldcs/stcs
// hints collapse MLP; do not reintroduce them).
// ---------------------------------------------------------------------------
constexpr int SCHUNK = 16;

__global__ __launch_bounds__(256) void lif_scan(
    float* __restrict__ spikes,      // [B,T,H]
    float* __restrict__ mem_final)   // [B,H]
{
    const int idx = blockIdx.x * blockDim.x + threadIdx.x;  // over B*H
    const int b = idx / HDIM;
    const int h = idx % HDIM;

    const float* Ip = g_I + (size_t)b * TDIM * HDIM + h;
    float* Sp = spikes + (size_t)b * TDIM * HDIM + h;

    float mem = 0.0f;
    for (int tb = 0; tb < TDIM; tb += SCHUNK) {
        float v[SCHUNK];
        #pragma unroll
        for (int j = 0; j < SCHUNK; j++)
            v[j] = Ip[(size_t)(tb + j) * HDIM];          // 16 independent LDGs

        #pragma unroll
        for (int j = 0; j < SCHUNK; j++) {
            mem = __fadd_rn(__fmul_rn(ALPHA, mem), v[j]);
            const bool fire = (mem >= 1.0f);
            Sp[(size_t)(tb + j) * HDIM] = fire ? 1.0f : 0.0f;
            mem = fire ? 0.0f : mem;
        }
    }
    mem_final[idx] = mem;
}

// ---------------------------------------------------------------------------
extern "C" void kernel_launch(void* const* d_in, const int* in_sizes, int n_in,
                              void* d_out, int out_size)
{
    const float* x  = (const float*)d_in[0];   // [B,T,IN]
    const float* W  = (const float*)d_in[1];   // [HID,IN]
    const float* b  = (const float*)d_in[2];   // [HID]

    float* out      = (float*)d_out;
    float* spikes   = out;                                   // B*T*H floats
    float* mem_fin  = out + (size_t)MTOT * HDIM;             // B*H floats

    // GEMM: I = x @ W^T + b   (Eigen kc=1016 ordering, FFMA2 v6 — frozen)
    dim3 gemmGrid(HDIM / BN, MTOT / BM);   // (8, 256)
    sgemm_nt_bias_eigen_f32x2<<<gemmGrid, 256>>>(x, W, b);

    // LIF scan over T (chunked-prefetch v2)
    lif_scan<<<(BDIM * HDIM) / 256, 256>>>(spikes, mem_fin);
}